// round 7
// baseline (speedup 1.0000x reference)
#include <cuda_runtime.h>
#include <cuda_bf16.h>
#include <math.h>
#include <stdint.h>

#define SS   8
#define CC   256
#define HH   23
#define WW   23
#define NFL  529
#define PP   529
#define PSTR 576            // padded K for transpose GEMM (multiple of 32)
#define CKD  2304
#define DHW  45

// GEMM tiling: block 128(M) x 96(N), K-tile 32, 4 warps (2x2), warp 64x48
#define BM   128
#define BN   96
#define BK   32
#define RSTR 80             // smem row stride bytes (32 bf16 = 64B + 16B pad)
#define ASZ  (BM * RSTR)    // 10240
#define BSZ  (BN * RSTR)    // 7680
#define STG  (2 * ASZ + 2 * BSZ)   // 35840 per stage
#define SMEMG (2 * STG)            // 71680

// ---- device-global scratch ----
__device__ float g_f[SS * NFL * CKD];
__device__ float g_grad[SS * NFL * CKD];
__device__ float g_wm[SS * NFL * PSTR];
__device__ __nv_bfloat16 g_fh[SS * NFL * CKD],  g_fl[SS * NFL * CKD];
__device__ __nv_bfloat16 g_gh[SS * NFL * CKD],  g_gl[SS * NFL * CKD];
__device__ __nv_bfloat16 g_rh[SS * NFL * PSTR], g_rl[SS * NFL * PSTR];
__device__ __nv_bfloat16 g_ch[SS * CKD * PSTR], g_cl[SS * CKD * PSTR];          // im2col  [ck][p]
__device__ __nv_bfloat16 g_th[(size_t)SS * PP * CKD], g_tl[(size_t)SS * PP * CKD]; // im2colT [p][ck]
__device__ float g_num[2 * SS * NFL];   // per-iteration
__device__ float g_den[2 * SS * NFL];
__device__ float g_lbl[DHW * DHW];
__device__ float g_sp[DHW * DHW];

// ---------------------------------------------------------------------------
__device__ __forceinline__ void splitbf(float v, __nv_bfloat16& h, __nv_bfloat16& l) {
    h = __float2bfloat16(v);
    l = __float2bfloat16(v - __bfloat162float(h));
}

__global__ void k_tables(const float* __restrict__ wl, const float* __restrict__ ws) {
    int i = blockIdx.x * blockDim.x + threadIdx.x;
    if (i >= DHW * DHW) return;
    int a = i / DHW, b = i - a * DHW;
    float da = (float)a - 22.0f, db = (float)b - 22.0f;
    float t = sqrtf(da * da + db * db) * 2.0f;
    float lab = 0.0f, sp = 0.0f;
#pragma unroll
    for (int k = 0; k < 9; k++) {
        float v = fmaxf(0.0f, 1.0f - fabsf(t - (float)k));
        lab += wl[k] * v; sp += ws[k] * v;
    }
    float v9 = fminf(fmaxf(t - 8.0f, 0.0f), 1.0f);
    lab += wl[9] * v9; sp += ws[9] * v9;
    g_lbl[i] = lab; g_sp[i] = sp;
}

__global__ void k_zero() {
    int i = blockIdx.x * blockDim.x + threadIdx.x;
    if (i < 2 * SS * NFL) { g_num[i] = 0.0f; g_den[i] = 0.0f; }
}

__device__ __forceinline__ float im2col_val(const float* __restrict__ feat,
                                            int s, int ck, int p) {
    int c = ck / 9, r = ck - c * 9;
    int ky = r / 3, kx = r - ky * 3;
    int y = p / WW, x = p - (p / WW) * WW;
    int yy = y + ky - 1, xx = x + kx - 1;
    if (yy < 0 || yy >= HH || xx < 0 || xx >= WW) return 0.0f;
    return feat[(((size_t)s * CC + c) * HH + yy) * WW + xx];
}

__global__ __launch_bounds__(256) void k_im2col(const float* __restrict__ feat) {
    size_t i = (size_t)blockIdx.x * 256 + threadIdx.x;
    const size_t total = (size_t)SS * CKD * PSTR;
    if (i >= total) return;
    int s  = (int)(i / ((size_t)CKD * PSTR));
    int r  = (int)(i - (size_t)s * CKD * PSTR);
    int ck = r / PSTR;
    int p  = r - ck * PSTR;
    float v = (p < PP) ? im2col_val(feat, s, ck, p) : 0.0f;
    splitbf(v, g_ch[i], g_cl[i]);
}

__global__ __launch_bounds__(256) void k_im2colT(const float* __restrict__ feat) {
    size_t i = (size_t)blockIdx.x * 256 + threadIdx.x;
    const size_t total = (size_t)SS * PP * CKD;
    if (i >= total) return;
    int s  = (int)(i / ((size_t)PP * CKD));
    int r  = (int)(i - (size_t)s * PP * CKD);
    int p  = r / CKD;
    int ck = r - p * CKD;
    splitbf(im2col_val(feat, s, ck, p), g_th[i], g_tl[i]);
}

__global__ __launch_bounds__(256) void k_split(const float* __restrict__ src,
                                               __nv_bfloat16* __restrict__ h,
                                               __nv_bfloat16* __restrict__ l) {
    size_t i = (size_t)blockIdx.x * 256 + threadIdx.x;
    const size_t total = (size_t)SS * NFL * CKD;
    if (i >= total) return;
    splitbf(src[i], h[i], l[i]);
}

// ---------------------------------------------------------------------------
__device__ __forceinline__ void ldsm4(unsigned* r, unsigned addr) {
    asm volatile("ldmatrix.sync.aligned.m8n8.x4.shared.b16 {%0,%1,%2,%3}, [%4];"
                 : "=r"(r[0]), "=r"(r[1]), "=r"(r[2]), "=r"(r[3]) : "r"(addr));
}
__device__ __forceinline__ void mmabf(float* d, const unsigned* a, const unsigned* b) {
    asm volatile(
        "mma.sync.aligned.m16n8k16.row.col.f32.bf16.bf16.f32 "
        "{%0,%1,%2,%3}, {%4,%5,%6,%7}, {%8,%9}, {%0,%1,%2,%3};"
        : "+f"(d[0]), "+f"(d[1]), "+f"(d[2]), "+f"(d[3])
        : "r"(a[0]), "r"(a[1]), "r"(a[2]), "r"(a[3]), "r"(b[0]), "r"(b[1]));
}
__device__ __forceinline__ void cp16(unsigned sdst, const void* gsrc, bool pred) {
    int sz = pred ? 16 : 0;
    asm volatile("cp.async.cg.shared.global [%0], [%1], 16, %2;\n"
                 :: "r"(sdst), "l"(gsrc), "r"(sz));
}

// ---------------------------------------------------------------------------
// C[M x N] = A * B^T, A/B presplit bf16 (hi,lo), 3-term compensated mma.
// MODE 0: A=filter(h,l), B=colT, K=CKD, N=PP  -> residual epilogue
// MODE 1: A=grad(h,l),   B=colT, K=CKD, N=PP  -> alpha_den epilogue
// MODE 2: A=resid(h,l),  B=col,  K=PSTR,N=CKD -> grad + alpha_num epilogue
// Block 128x96, 4 warps (2x2), warp tile 64x48.
// ---------------------------------------------------------------------------
template <int MODE>
__global__ __launch_bounds__(128, 3) void k_gemm(const __nv_bfloat16* __restrict__ Ahg,
                                                 const __nv_bfloat16* __restrict__ Alg,
                                                 const float* __restrict__ fsrc,
                                                 const float* __restrict__ p_reg,
                                                 int iter) {
    constexpr int K   = (MODE == 2) ? PSTR : CKD;
    constexpr int LD  = K;
    constexpr int NBR = (MODE == 2) ? CKD : PP;
    constexpr int KT  = K / BK;              // 72 or 18

    const int s  = blockIdx.z;
    const int m0 = blockIdx.y * BM;
    const int n0 = blockIdx.x * BN;
    const int tid = threadIdx.x;
    const int w = tid >> 5, lane = tid & 31;
    const int g = lane >> 2, t = lane & 3;
    const int wm0 = (w >> 1) * 64;           // warp M offset (0/64)
    const int wn0 = (w & 1) * 48;            // warp N offset (0/48)

    const __nv_bfloat16* Ah = Ahg + (size_t)s * NFL * LD;
    const __nv_bfloat16* Al = Alg + (size_t)s * NFL * LD;
    const __nv_bfloat16* Bh = (MODE == 2) ? (g_ch + (size_t)s * CKD * PSTR)
                                          : (g_th + (size_t)s * PP * CKD);
    const __nv_bfloat16* Bl = (MODE == 2) ? (g_cl + (size_t)s * CKD * PSTR)
                                          : (g_tl + (size_t)s * PP * CKD);

    extern __shared__ char dsm[];
    const unsigned sb0 = (unsigned)__cvta_generic_to_shared(dsm);
    // stage layout: [Ah ASZ][Al ASZ][Bh BSZ][Bl BSZ]

    float acc[4][6][4] = {};

    auto load_stage = [&](int kt, int buf) {
        const unsigned st = sb0 + buf * STG;
        const int k0 = kt * BK;
        // A arrays: 512 chunks of 16B each -> 4 per thread per array
#pragma unroll
        for (int arr = 0; arr < 2; arr++) {
            const __nv_bfloat16* G = arr ? Al : Ah;
            const unsigned tb = st + arr * ASZ;
#pragma unroll
            for (int q = 0; q < 4; q++) {
                int ch  = q * 128 + tid;
                int row = ch >> 2, c16 = ch & 3;
                bool pr = (m0 + row) < NFL;
                const void* src = G + (size_t)(pr ? m0 + row : 0) * LD + k0 + c16 * 8;
                cp16(tb + row * RSTR + c16 * 16, src, pr);
            }
        }
        // B arrays: 384 chunks -> 3 per thread per array
#pragma unroll
        for (int arr = 0; arr < 2; arr++) {
            const __nv_bfloat16* G = arr ? Bl : Bh;
            const unsigned tb = st + 2 * ASZ + arr * BSZ;
#pragma unroll
            for (int q = 0; q < 3; q++) {
                int ch  = q * 128 + tid;
                int row = ch >> 2, c16 = ch & 3;
                bool pr = (n0 + row) < NBR;
                const void* src = G + (size_t)(pr ? n0 + row : 0) * LD + k0 + c16 * 8;
                cp16(tb + row * RSTR + c16 * 16, src, pr);
            }
        }
        asm volatile("cp.async.commit_group;\n");
    };

    load_stage(0, 0);
    if (KT > 1) load_stage(1, 1);

    for (int kt = 0; kt < KT; kt++) {
        if (kt + 1 < KT)
            asm volatile("cp.async.wait_group 1;\n");
        else
            asm volatile("cp.async.wait_group 0;\n");
        __syncthreads();
        const unsigned st = sb0 + (kt & 1) * STG;

#pragma unroll
        for (int ks = 0; ks < BK; ks += 16) {
            unsigned ah[4][4], al[4][4], bh[6][2], bl[6][2];
            // A fragments: 16x16 per ldsm4
            {
                int r = (lane & 7) + ((lane >> 3) & 1) * 8;
                int c = ks + (lane >> 4) * 8;
                unsigned off = (unsigned)((wm0 + r) * RSTR + c * 2);
#pragma unroll
                for (int im = 0; im < 4; im++) {
                    ldsm4(ah[im], st + off + im * 16 * RSTR);
                    ldsm4(al[im], st + ASZ + off + im * 16 * RSTR);
                }
            }
            // B fragments: 16 n-rows x 16 k per ldsm4 -> three n16 blocks
            {
                int q = lane >> 3;
                int r = (lane & 7) + (q >> 1) * 8;
                int c = ks + (q & 1) * 8;
                unsigned off = (unsigned)((wn0 + r) * RSTR + c * 2);
#pragma unroll
                for (int inp = 0; inp < 3; inp++) {
                    unsigned rv[4];
                    ldsm4(rv, st + 2 * ASZ + off + inp * 16 * RSTR);
                    bh[inp * 2][0] = rv[0]; bh[inp * 2][1] = rv[1];
                    bh[inp * 2 + 1][0] = rv[2]; bh[inp * 2 + 1][1] = rv[3];
                    ldsm4(rv, st + 2 * ASZ + BSZ + off + inp * 16 * RSTR);
                    bl[inp * 2][0] = rv[0]; bl[inp * 2][1] = rv[1];
                    bl[inp * 2 + 1][0] = rv[2]; bl[inp * 2 + 1][1] = rv[3];
                }
            }
#pragma unroll
            for (int im = 0; im < 4; im++)
#pragma unroll
                for (int in = 0; in < 6; in++) {
                    mmabf(acc[im][in], al[im], bh[in]);
                    mmabf(acc[im][in], ah[im], bl[in]);
                    mmabf(acc[im][in], ah[im], bh[in]);
                }
        }
        __syncthreads();
        if (kt + 2 < KT) load_stage(kt + 2, kt & 1);
    }

    float* numI = g_num + iter * SS * NFL;
    float* denI = g_den + iter * SS * NFL;

    // ---- epilogues ----
    if (MODE == 0) {
#pragma unroll
        for (int im = 0; im < 4; im++)
#pragma unroll
            for (int in = 0; in < 6; in++)
#pragma unroll
                for (int e = 0; e < 4; e++) {
                    int m = m0 + wm0 + im * 16 + g + ((e >> 1) << 3);
                    int p = n0 + wn0 + in * 8 + 2 * t + (e & 1);
                    if (m >= NFL || p >= PSTR) continue;
                    size_t off = ((size_t)s * NFL + m) * PSTR + p;
                    if (p >= PP) {
                        g_rh[off] = __float2bfloat16(0.0f);
                        g_rl[off] = __float2bfloat16(0.0f);
                        g_wm[off] = 0.0f;
                        continue;
                    }
                    int i0 = m / WW, i1 = m - i0 * WW;
                    int j0 = p / WW, j1 = p - j0 * WW;
                    int tl = (22 - i0 + j0) * DHW + (22 - i1 + j1);
                    float lab = g_lbl[tl];
                    float sw  = g_sp[tl];
                    float sc = acc[im][in][e];
                    float act, mask;
                    if (m == p) { act = sc; mask = 1.0f; }
                    else {
                        act  = fmaxf(sc, 0.0f);
                        mask = sc > 0.0f ? 1.0f : (sc < 0.0f ? 0.0f : 0.5f);
                    }
                    float rv = mask * sw * sw * (act - lab);
                    splitbf(rv, g_rh[off], g_rl[off]);
                    g_wm[off] = mask * sw;
                }
    } else if (MODE == 1) {
        float rs[4][2] = {};
#pragma unroll
        for (int im = 0; im < 4; im++)
#pragma unroll
            for (int in = 0; in < 6; in++)
#pragma unroll
                for (int e = 0; e < 4; e++) {
                    int m = m0 + wm0 + im * 16 + g + ((e >> 1) << 3);
                    int p = n0 + wn0 + in * 8 + 2 * t + (e & 1);
                    if (m >= NFL || p >= PP) continue;
                    float wmv = g_wm[((size_t)s * NFL + m) * PSTR + p];
                    float v = wmv * acc[im][in][e];
                    rs[im][e >> 1] += v * v;
                }
#pragma unroll
        for (int im = 0; im < 4; im++)
#pragma unroll
            for (int h = 0; h < 2; h++) {
                float sum = rs[im][h];
                sum += __shfl_xor_sync(0xffffffffu, sum, 1);
                sum += __shfl_xor_sync(0xffffffffu, sum, 2);
                if (t == 0) {
                    int m = m0 + wm0 + im * 16 + g + h * 8;
                    if (m < NFL) atomicAdd(&denI[s * NFL + m], sum);
                }
            }
    } else {
        float fr = p_reg[0];
        float regw = fmaxf(fr * fr, 1e-10f);
        float rs[4][2] = {};
#pragma unroll
        for (int im = 0; im < 4; im++)
#pragma unroll
            for (int in = 0; in < 6; in++)
#pragma unroll
                for (int e = 0; e < 4; e++) {
                    int m  = m0 + wm0 + im * 16 + g + ((e >> 1) << 3);
                    int ck = n0 + wn0 + in * 8 + 2 * t + (e & 1);
                    if (m >= NFL) continue;
                    size_t off = ((size_t)s * NFL + m) * CKD + ck;
                    float gg = acc[im][in][e] + regw * fsrc[off];
                    g_grad[off] = gg;
                    splitbf(gg, g_gh[off], g_gl[off]);
                    rs[im][e >> 1] += gg * gg;
                }
#pragma unroll
        for (int im = 0; im < 4; im++)
#pragma unroll
            for (int h = 0; h < 2; h++) {
                float sum = rs[im][h];
                sum += __shfl_xor_sync(0xffffffffu, sum, 1);
                sum += __shfl_xor_sync(0xffffffffu, sum, 2);
                if (t == 0) {
                    int m = m0 + wm0 + im * 16 + g + h * 8;
                    if (m < NFL) atomicAdd(&numI[s * NFL + m], sum);
                }
            }
    }
}

// ---------------------------------------------------------------------------
__global__ __launch_bounds__(256) void k_update(const float* __restrict__ fsrc,
                                                float* __restrict__ fdst,
                                                __nv_bfloat16* __restrict__ fh,
                                                __nv_bfloat16* __restrict__ fl,
                                                const float* __restrict__ p_step,
                                                const float* __restrict__ p_reg,
                                                int iter) {
    size_t i = (size_t)blockIdx.x * blockDim.x + threadIdx.x;
    const size_t total4 = (size_t)SS * NFL * CKD / 4;
    if (i >= total4) return;
    size_t e0 = i * 4;
    int row = (int)(e0 / CKD);
    float num = g_num[iter * SS * NFL + row];
    float den = g_den[iter * SS * NFL + row];
    float fr = p_reg[0];
    float regw = fmaxf(fr * fr, 1e-10f);
    float denom = fmaxf(den + regw * num, 1e-8f);
    float alpha = num / denom;
    float sa = expf(p_step[0]) * alpha;
    float4 f4 = *reinterpret_cast<const float4*>(fsrc + e0);
    float4 g4 = *reinterpret_cast<const float4*>(&g_grad[e0]);
    float4 o;
    o.x = f4.x - sa * g4.x;
    o.y = f4.y - sa * g4.y;
    o.z = f4.z - sa * g4.z;
    o.w = f4.w - sa * g4.w;
    *reinterpret_cast<float4*>(fdst + e0) = o;
    splitbf(o.x, fh[e0 + 0], fl[e0 + 0]);
    splitbf(o.y, fh[e0 + 1], fl[e0 + 1]);
    splitbf(o.z, fh[e0 + 2], fl[e0 + 2]);
    splitbf(o.w, fh[e0 + 3], fl[e0 + 3]);
}

// ---------------------------------------------------------------------------
extern "C" void kernel_launch(void* const* d_in, const int* in_sizes, int n_in,
                              void* d_out, int out_size) {
    const float* fin   = (const float*)d_in[0];
    const float* feat  = (const float*)d_in[1];
    const float* wl    = (const float*)d_in[2];
    const float* ws    = (const float*)d_in[3];
    const float* pstep = (const float*)d_in[4];
    const float* preg  = (const float*)d_in[5];

    float* pf = nullptr;
    cudaGetSymbolAddress((void**)&pf, g_f);
    __nv_bfloat16 *pfh = nullptr, *pfl = nullptr, *pgh = nullptr, *pgl = nullptr,
                  *prh = nullptr, *prl = nullptr;
    cudaGetSymbolAddress((void**)&pfh, g_fh);
    cudaGetSymbolAddress((void**)&pfl, g_fl);
    cudaGetSymbolAddress((void**)&pgh, g_gh);
    cudaGetSymbolAddress((void**)&pgl, g_gl);
    cudaGetSymbolAddress((void**)&prh, g_rh);
    cudaGetSymbolAddress((void**)&prl, g_rl);

    static bool attr_done = false;
    if (!attr_done) {
        cudaFuncSetAttribute(k_gemm<0>, cudaFuncAttributeMaxDynamicSharedMemorySize, SMEMG);
        cudaFuncSetAttribute(k_gemm<1>, cudaFuncAttributeMaxDynamicSharedMemorySize, SMEMG);
        cudaFuncSetAttribute(k_gemm<2>, cudaFuncAttributeMaxDynamicSharedMemorySize, SMEMG);
        attr_done = true;
    }

    dim3 gfwd(PSTR / BN, 5, SS);        // (6, 5, 8)
    dim3 gbwd(CKD / BN, 5, SS);         // (24, 5, 8)
    int upd_blocks = (int)(((size_t)SS * NFL * CKD / 4 + 255) / 256);
    int spl_blocks = (int)(((size_t)SS * NFL * CKD + 255) / 256);
    int i2c_blocks  = (int)(((size_t)SS * CKD * PSTR + 255) / 256);
    int i2ct_blocks = (int)(((size_t)SS * PP * CKD + 255) / 256);

    // setup (5 launches) so launch #6 = k_gemm<0> for ncu -s 5 -c 1
    k_tables<<<8, 256>>>(wl, ws);
    k_zero<<<34, 256>>>();
    k_im2col<<<i2c_blocks, 256>>>(feat);
    k_im2colT<<<i2ct_blocks, 256>>>(feat);
    k_split<<<spl_blocks, 256>>>(fin, pfh, pfl);

    for (int it = 0; it < 2; ++it) {
        const float* fcur = (it == 0) ? fin : pf;
        float* fnext = (it == 0) ? pf : (float*)d_out;

        k_gemm<0><<<gfwd, 128, SMEMG>>>(pfh, pfl, nullptr, preg, it);  // scores -> resid
        k_gemm<2><<<gbwd, 128, SMEMG>>>(prh, prl, fcur, preg, it);     // grad + num
        k_gemm<1><<<gfwd, 128, SMEMG>>>(pgh, pgl, nullptr, preg, it);  // den
        k_update<<<upd_blocks, 256>>>(fcur, fnext, pfh, pfl, pstep, preg, it);
    }
}

// round 8
// speedup vs baseline: 1.1242x; 1.1242x over previous
#include <cuda_runtime.h>
#include <cuda_bf16.h>
#include <math.h>
#include <stdint.h>

#define SS   8
#define CC   256
#define HH   23
#define WW   23
#define NFL  529
#define PP   529
#define PSTR 576            // padded K for transpose GEMM (multiple of 32)
#define CKD  2304
#define DHW  45

// GEMM tiling: block 96(M) x 96(N), K-tile 32, 4 warps (2x2), warp 48x48
#define BM   96
#define BN   96
#define BK   32
#define RSTR 80             // smem row stride bytes (32 bf16 = 64B + 16B pad)
#define ASZ  (BM * RSTR)    // 7680
#define BSZ  (BN * RSTR)    // 7680
#define STG  (2 * ASZ + 2 * BSZ)   // 30720 per stage
#define SMEMG (2 * STG)            // 61440

// ---- device-global scratch ----
__device__ float g_f[SS * NFL * CKD];
__device__ float g_grad[SS * NFL * CKD];
__device__ float g_wm[SS * NFL * PSTR];
__device__ __nv_bfloat16 g_fh[SS * NFL * CKD],  g_fl[SS * NFL * CKD];
__device__ __nv_bfloat16 g_gh[SS * NFL * CKD],  g_gl[SS * NFL * CKD];
__device__ __nv_bfloat16 g_rh[SS * NFL * PSTR], g_rl[SS * NFL * PSTR];
__device__ __nv_bfloat16 g_ch[SS * CKD * PSTR], g_cl[SS * CKD * PSTR];          // im2col  [ck][p]
__device__ __nv_bfloat16 g_th[(size_t)SS * PP * CKD], g_tl[(size_t)SS * PP * CKD]; // im2colT [p][ck]
__device__ float g_num[2 * SS * NFL];   // per-iteration
__device__ float g_den[2 * SS * NFL];
__device__ float g_lbl[DHW * DHW];
__device__ float g_sp[DHW * DHW];

// ---------------------------------------------------------------------------
__device__ __forceinline__ void splitbf(float v, __nv_bfloat16& h, __nv_bfloat16& l) {
    h = __float2bfloat16(v);
    l = __float2bfloat16(v - __bfloat162float(h));
}

// fused: tables + zero num/den
__global__ void k_setup(const float* __restrict__ wl, const float* __restrict__ ws) {
    int i = blockIdx.x * blockDim.x + threadIdx.x;
    if (i < 2 * SS * NFL) { g_num[i] = 0.0f; g_den[i] = 0.0f; }
    if (i >= DHW * DHW) return;
    int a = i / DHW, b = i - a * DHW;
    float da = (float)a - 22.0f, db = (float)b - 22.0f;
    float t = sqrtf(da * da + db * db) * 2.0f;
    float lab = 0.0f, sp = 0.0f;
#pragma unroll
    for (int k = 0; k < 9; k++) {
        float v = fmaxf(0.0f, 1.0f - fabsf(t - (float)k));
        lab += wl[k] * v; sp += ws[k] * v;
    }
    float v9 = fminf(fmaxf(t - 8.0f, 0.0f), 1.0f);
    lab += wl[9] * v9; sp += ws[9] * v9;
    g_lbl[i] = lab; g_sp[i] = sp;
}

__device__ __forceinline__ float im2col_val(const float* __restrict__ feat,
                                            int s, int ck, int p) {
    int c = ck / 9, r = ck - c * 9;
    int ky = r / 3, kx = r - ky * 3;
    int y = p / WW, x = p - (p / WW) * WW;
    int yy = y + ky - 1, xx = x + kx - 1;
    if (yy < 0 || yy >= HH || xx < 0 || xx >= WW) return 0.0f;
    return feat[(((size_t)s * CC + c) * HH + yy) * WW + xx];
}

// fused: im2col ([ck][p], PSTR rows) + im2colT ([p][ck])
__global__ __launch_bounds__(256) void k_cols(const float* __restrict__ feat) {
    const size_t total1 = (size_t)SS * CKD * PSTR;
    const size_t total2 = (size_t)SS * PP * CKD;
    size_t i = (size_t)blockIdx.x * 256 + threadIdx.x;
    if (i < total1) {
        int s  = (int)(i / ((size_t)CKD * PSTR));
        int r  = (int)(i - (size_t)s * CKD * PSTR);
        int ck = r / PSTR;
        int p  = r - ck * PSTR;
        float v = (p < PP) ? im2col_val(feat, s, ck, p) : 0.0f;
        splitbf(v, g_ch[i], g_cl[i]);
    } else if (i < total1 + total2) {
        size_t j = i - total1;
        int s  = (int)(j / ((size_t)PP * CKD));
        int r  = (int)(j - (size_t)s * PP * CKD);
        int p  = r / CKD;
        int ck = r - p * CKD;
        splitbf(im2col_val(feat, s, ck, p), g_th[j], g_tl[j]);
    }
}

__global__ __launch_bounds__(256) void k_split(const float* __restrict__ src,
                                               __nv_bfloat16* __restrict__ h,
                                               __nv_bfloat16* __restrict__ l) {
    size_t i = (size_t)blockIdx.x * 256 + threadIdx.x;
    const size_t total = (size_t)SS * NFL * CKD;
    if (i >= total) return;
    splitbf(src[i], h[i], l[i]);
}

// ---------------------------------------------------------------------------
__device__ __forceinline__ void ldsm4(unsigned* r, unsigned addr) {
    asm volatile("ldmatrix.sync.aligned.m8n8.x4.shared.b16 {%0,%1,%2,%3}, [%4];"
                 : "=r"(r[0]), "=r"(r[1]), "=r"(r[2]), "=r"(r[3]) : "r"(addr));
}
__device__ __forceinline__ void mmabf(float* d, const unsigned* a, const unsigned* b) {
    asm volatile(
        "mma.sync.aligned.m16n8k16.row.col.f32.bf16.bf16.f32 "
        "{%0,%1,%2,%3}, {%4,%5,%6,%7}, {%8,%9}, {%0,%1,%2,%3};"
        : "+f"(d[0]), "+f"(d[1]), "+f"(d[2]), "+f"(d[3])
        : "r"(a[0]), "r"(a[1]), "r"(a[2]), "r"(a[3]), "r"(b[0]), "r"(b[1]));
}
__device__ __forceinline__ void cp16(unsigned sdst, const void* gsrc, bool pred) {
    int sz = pred ? 16 : 0;
    asm volatile("cp.async.cg.shared.global [%0], [%1], 16, %2;\n"
                 :: "r"(sdst), "l"(gsrc), "r"(sz));
}

// ---------------------------------------------------------------------------
// C[M x N] = A * B^T, A/B presplit bf16 (hi,lo), 3-term compensated mma.
// MODE 0: A=filter(h,l), B=colT, K=CKD, N=PP  -> residual epilogue
// MODE 1: A=grad(h,l),   B=colT, K=CKD, N=PP  -> alpha_den epilogue
// MODE 2: A=resid(h,l),  B=col,  K=PSTR,N=CKD -> grad + alpha_num epilogue
// Block 96x96, 4 warps (2x2), warp tile 48x48.
// ---------------------------------------------------------------------------
template <int MODE>
__global__ __launch_bounds__(128, 3) void k_gemm(const __nv_bfloat16* __restrict__ Ahg,
                                                 const __nv_bfloat16* __restrict__ Alg,
                                                 const float* __restrict__ fsrc,
                                                 const float* __restrict__ p_reg,
                                                 int iter) {
    constexpr int K   = (MODE == 2) ? PSTR : CKD;
    constexpr int LD  = K;
    constexpr int NBR = (MODE == 2) ? CKD : PP;
    constexpr int KT  = K / BK;              // 72 or 18

    const int s  = blockIdx.z;
    const int m0 = blockIdx.y * BM;
    const int n0 = blockIdx.x * BN;
    const int tid = threadIdx.x;
    const int w = tid >> 5, lane = tid & 31;
    const int g = lane >> 2, t = lane & 3;
    const int wm0 = (w >> 1) * 48;           // warp M offset (0/48)
    const int wn0 = (w & 1) * 48;            // warp N offset (0/48)

    const __nv_bfloat16* Ah = Ahg + (size_t)s * NFL * LD;
    const __nv_bfloat16* Al = Alg + (size_t)s * NFL * LD;
    const __nv_bfloat16* Bh = (MODE == 2) ? (g_ch + (size_t)s * CKD * PSTR)
                                          : (g_th + (size_t)s * PP * CKD);
    const __nv_bfloat16* Bl = (MODE == 2) ? (g_cl + (size_t)s * CKD * PSTR)
                                          : (g_tl + (size_t)s * PP * CKD);

    extern __shared__ char dsm[];
    const unsigned sb0 = (unsigned)__cvta_generic_to_shared(dsm);
    // stage layout: [Ah ASZ][Al ASZ][Bh BSZ][Bl BSZ]

    float acc[3][6][4] = {};

    auto load_stage = [&](int kt, int buf) {
        const unsigned st = sb0 + buf * STG;
        const int k0 = kt * BK;
        // each array: 96 rows x 4 chunks(16B) = 384 chunks -> 3 per thread
#pragma unroll
        for (int arr = 0; arr < 4; arr++) {
            const __nv_bfloat16* G = (arr == 0) ? Ah : (arr == 1) ? Al
                                   : (arr == 2) ? Bh : Bl;
            const int r0   = (arr < 2) ? m0 : n0;
            const int rmax = (arr < 2) ? NFL : NBR;
            const unsigned tb = st + arr * ASZ;
#pragma unroll
            for (int q = 0; q < 3; q++) {
                int ch  = q * 128 + tid;
                int row = ch >> 2, c16 = ch & 3;
                bool pr = (r0 + row) < rmax;
                const void* src = G + (size_t)(pr ? r0 + row : 0) * LD + k0 + c16 * 8;
                cp16(tb + row * RSTR + c16 * 16, src, pr);
            }
        }
        asm volatile("cp.async.commit_group;\n");
    };

    load_stage(0, 0);
    if (KT > 1) load_stage(1, 1);

    for (int kt = 0; kt < KT; kt++) {
        if (kt + 1 < KT)
            asm volatile("cp.async.wait_group 1;\n");
        else
            asm volatile("cp.async.wait_group 0;\n");
        __syncthreads();
        const unsigned st = sb0 + (kt & 1) * STG;

#pragma unroll
        for (int ks = 0; ks < BK; ks += 16) {
            unsigned ah[3][4], al[3][4], bh[6][2], bl[6][2];
            // A fragments: 16x16 per ldsm4 (3 m16 blocks)
            {
                int r = (lane & 7) + ((lane >> 3) & 1) * 8;
                int c = ks + (lane >> 4) * 8;
                unsigned off = (unsigned)((wm0 + r) * RSTR + c * 2);
#pragma unroll
                for (int im = 0; im < 3; im++) {
                    ldsm4(ah[im], st + off + im * 16 * RSTR);
                    ldsm4(al[im], st + ASZ + off + im * 16 * RSTR);
                }
            }
            // B fragments: 16 n-rows x 16 k per ldsm4 -> three n16 blocks
            {
                int q = lane >> 3;
                int r = (lane & 7) + (q >> 1) * 8;
                int c = ks + (q & 1) * 8;
                unsigned off = (unsigned)((wn0 + r) * RSTR + c * 2);
#pragma unroll
                for (int inp = 0; inp < 3; inp++) {
                    unsigned rv[4];
                    ldsm4(rv, st + 2 * ASZ + off + inp * 16 * RSTR);
                    bh[inp * 2][0] = rv[0]; bh[inp * 2][1] = rv[1];
                    bh[inp * 2 + 1][0] = rv[2]; bh[inp * 2 + 1][1] = rv[3];
                    ldsm4(rv, st + 3 * ASZ + off + inp * 16 * RSTR);
                    bl[inp * 2][0] = rv[0]; bl[inp * 2][1] = rv[1];
                    bl[inp * 2 + 1][0] = rv[2]; bl[inp * 2 + 1][1] = rv[3];
                }
            }
#pragma unroll
            for (int im = 0; im < 3; im++)
#pragma unroll
                for (int in = 0; in < 6; in++) {
                    mmabf(acc[im][in], al[im], bh[in]);
                    mmabf(acc[im][in], ah[im], bl[in]);
                    mmabf(acc[im][in], ah[im], bh[in]);
                }
        }
        __syncthreads();
        if (kt + 2 < KT) load_stage(kt + 2, kt & 1);
    }

    float* numI = g_num + iter * SS * NFL;
    float* denI = g_den + iter * SS * NFL;

    // ---- epilogues ----
    if (MODE == 0) {
#pragma unroll
        for (int im = 0; im < 3; im++)
#pragma unroll
            for (int in = 0; in < 6; in++)
#pragma unroll
                for (int e = 0; e < 4; e++) {
                    int m = m0 + wm0 + im * 16 + g + ((e >> 1) << 3);
                    int p = n0 + wn0 + in * 8 + 2 * t + (e & 1);
                    if (m >= NFL || p >= PSTR) continue;
                    size_t off = ((size_t)s * NFL + m) * PSTR + p;
                    if (p >= PP) {
                        g_rh[off] = __float2bfloat16(0.0f);
                        g_rl[off] = __float2bfloat16(0.0f);
                        g_wm[off] = 0.0f;
                        continue;
                    }
                    int i0 = m / WW, i1 = m - i0 * WW;
                    int j0 = p / WW, j1 = p - j0 * WW;
                    int tl = (22 - i0 + j0) * DHW + (22 - i1 + j1);
                    float lab = g_lbl[tl];
                    float sw  = g_sp[tl];
                    float sc = acc[im][in][e];
                    float act, mask;
                    if (m == p) { act = sc; mask = 1.0f; }
                    else {
                        act  = fmaxf(sc, 0.0f);
                        mask = sc > 0.0f ? 1.0f : (sc < 0.0f ? 0.0f : 0.5f);
                    }
                    float rv = mask * sw * sw * (act - lab);
                    splitbf(rv, g_rh[off], g_rl[off]);
                    g_wm[off] = mask * sw;
                }
    } else if (MODE == 1) {
        float rs[3][2] = {};
#pragma unroll
        for (int im = 0; im < 3; im++)
#pragma unroll
            for (int in = 0; in < 6; in++)
#pragma unroll
                for (int e = 0; e < 4; e++) {
                    int m = m0 + wm0 + im * 16 + g + ((e >> 1) << 3);
                    int p = n0 + wn0 + in * 8 + 2 * t + (e & 1);
                    if (m >= NFL || p >= PP) continue;
                    float wmv = g_wm[((size_t)s * NFL + m) * PSTR + p];
                    float v = wmv * acc[im][in][e];
                    rs[im][e >> 1] += v * v;
                }
#pragma unroll
        for (int im = 0; im < 3; im++)
#pragma unroll
            for (int h = 0; h < 2; h++) {
                float sum = rs[im][h];
                sum += __shfl_xor_sync(0xffffffffu, sum, 1);
                sum += __shfl_xor_sync(0xffffffffu, sum, 2);
                if (t == 0) {
                    int m = m0 + wm0 + im * 16 + g + h * 8;
                    if (m < NFL) atomicAdd(&denI[s * NFL + m], sum);
                }
            }
    } else {
        float fr = p_reg[0];
        float regw = fmaxf(fr * fr, 1e-10f);
        float rs[3][2] = {};
#pragma unroll
        for (int im = 0; im < 3; im++)
#pragma unroll
            for (int in = 0; in < 6; in++)
#pragma unroll
                for (int e = 0; e < 4; e++) {
                    int m  = m0 + wm0 + im * 16 + g + ((e >> 1) << 3);
                    int ck = n0 + wn0 + in * 8 + 2 * t + (e & 1);
                    if (m >= NFL) continue;
                    size_t off = ((size_t)s * NFL + m) * CKD + ck;
                    float gg = acc[im][in][e] + regw * fsrc[off];
                    g_grad[off] = gg;
                    splitbf(gg, g_gh[off], g_gl[off]);
                    rs[im][e >> 1] += gg * gg;
                }
#pragma unroll
        for (int im = 0; im < 3; im++)
#pragma unroll
            for (int h = 0; h < 2; h++) {
                float sum = rs[im][h];
                sum += __shfl_xor_sync(0xffffffffu, sum, 1);
                sum += __shfl_xor_sync(0xffffffffu, sum, 2);
                if (t == 0) {
                    int m = m0 + wm0 + im * 16 + g + h * 8;
                    if (m < NFL) atomicAdd(&numI[s * NFL + m], sum);
                }
            }
    }
}

// ---------------------------------------------------------------------------
__global__ __launch_bounds__(256) void k_update(const float* __restrict__ fsrc,
                                                float* __restrict__ fdst,
                                                __nv_bfloat16* __restrict__ fh,
                                                __nv_bfloat16* __restrict__ fl,
                                                const float* __restrict__ p_step,
                                                const float* __restrict__ p_reg,
                                                int iter) {
    size_t i = (size_t)blockIdx.x * blockDim.x + threadIdx.x;
    const size_t total4 = (size_t)SS * NFL * CKD / 4;
    if (i >= total4) return;
    size_t e0 = i * 4;
    int row = (int)(e0 / CKD);
    float num = g_num[iter * SS * NFL + row];
    float den = g_den[iter * SS * NFL + row];
    float fr = p_reg[0];
    float regw = fmaxf(fr * fr, 1e-10f);
    float denom = fmaxf(den + regw * num, 1e-8f);
    float alpha = num / denom;
    float sa = expf(p_step[0]) * alpha;
    float4 f4 = *reinterpret_cast<const float4*>(fsrc + e0);
    float4 g4 = *reinterpret_cast<const float4*>(&g_grad[e0]);
    float4 o;
    o.x = f4.x - sa * g4.x;
    o.y = f4.y - sa * g4.y;
    o.z = f4.z - sa * g4.z;
    o.w = f4.w - sa * g4.w;
    *reinterpret_cast<float4*>(fdst + e0) = o;
    splitbf(o.x, fh[e0 + 0], fl[e0 + 0]);
    splitbf(o.y, fh[e0 + 1], fl[e0 + 1]);
    splitbf(o.z, fh[e0 + 2], fl[e0 + 2]);
    splitbf(o.w, fh[e0 + 3], fl[e0 + 3]);
}

// ---------------------------------------------------------------------------
extern "C" void kernel_launch(void* const* d_in, const int* in_sizes, int n_in,
                              void* d_out, int out_size) {
    const float* fin   = (const float*)d_in[0];
    const float* feat  = (const float*)d_in[1];
    const float* wl    = (const float*)d_in[2];
    const float* ws    = (const float*)d_in[3];
    const float* pstep = (const float*)d_in[4];
    const float* preg  = (const float*)d_in[5];

    float* pf = nullptr;
    cudaGetSymbolAddress((void**)&pf, g_f);
    __nv_bfloat16 *pfh = nullptr, *pfl = nullptr, *pgh = nullptr, *pgl = nullptr,
                  *prh = nullptr, *prl = nullptr;
    cudaGetSymbolAddress((void**)&pfh, g_fh);
    cudaGetSymbolAddress((void**)&pfl, g_fl);
    cudaGetSymbolAddress((void**)&pgh, g_gh);
    cudaGetSymbolAddress((void**)&pgl, g_gl);
    cudaGetSymbolAddress((void**)&prh, g_rh);
    cudaGetSymbolAddress((void**)&prl, g_rl);

    static bool attr_done = false;
    if (!attr_done) {
        cudaFuncSetAttribute(k_gemm<0>, cudaFuncAttributeMaxDynamicSharedMemorySize, SMEMG);
        cudaFuncSetAttribute(k_gemm<1>, cudaFuncAttributeMaxDynamicSharedMemorySize, SMEMG);
        cudaFuncSetAttribute(k_gemm<2>, cudaFuncAttributeMaxDynamicSharedMemorySize, SMEMG);
        attr_done = true;
    }

    dim3 gfwd(PSTR / BN, 6, SS);        // (6, 6, 8) = 288
    dim3 gbwd(CKD / BN, 6, SS);         // (24, 6, 8) = 1152
    int upd_blocks = (int)(((size_t)SS * NFL * CKD / 4 + 255) / 256);
    int spl_blocks = (int)(((size_t)SS * NFL * CKD + 255) / 256);
    size_t cols_total = (size_t)SS * CKD * PSTR + (size_t)SS * PP * CKD;
    int cols_blocks = (int)((cols_total + 255) / 256);

    // 3 setup launches; k_gemm<0> is our 4th launch (matches ncu window offset)
    k_setup<<<34, 256>>>(wl, ws);
    k_cols<<<cols_blocks, 256>>>(feat);
    k_split<<<spl_blocks, 256>>>(fin, pfh, pfl);

    for (int it = 0; it < 2; ++it) {
        const float* fcur = (it == 0) ? fin : pf;
        float* fnext = (it == 0) ? pf : (float*)d_out;

        k_gemm<0><<<gfwd, 128, SMEMG>>>(pfh, pfl, nullptr, preg, it);  // scores -> resid
        k_gemm<2><<<gbwd, 128, SMEMG>>>(prh, prl, fcur, preg, it);     // grad + num
        k_gemm<1><<<gfwd, 128, SMEMG>>>(pgh, pgl, nullptr, preg, it);  // den
        k_update<<<upd_blocks, 256>>>(fcur, fnext, pfh, pfl, pstep, preg, it);
    }
}